// round 1
// baseline (speedup 1.0000x reference)
#include <cuda_runtime.h>
#include <cstdint>

// Problem constants
#define B_   8
#define C_   128
#define H_   64
#define W_   64
#define COUT 128
#define KO   18          // offset channels (2*3*3)
#define K2_  9
#define CK   1152        // C_*K2_

// ---------------- device scratch (no allocs allowed) ----------------
__device__ float g_off[B_ * KO * H_ * W_];     // offsets conv result, [b][ko][h][w]
__device__ float g_wT[CK * COUT];              // w_def transposed: [(c*9+k)][cout]

// ---------------- kernel 0: transpose w_def -> g_wT ----------------
__global__ void k_transpose_wdef(const float* __restrict__ w_def) {
    int i = blockIdx.x * blockDim.x + threadIdx.x;      // over COUT*CK
    if (i < COUT * CK) {
        int cout = i / CK;
        int ck   = i - cout * CK;
        g_wT[ck * COUT + cout] = w_def[i];
    }
}

// ---------------- kernel 1: offsets = conv3x3(x, w_off) + b_off ----------------
// grid = B_*H_ blocks (one output row each), blockDim = 128
// thread layout: g = tid>>5 (0..3) handles ko = g*5 .. g*5+4 (padded to 20),
//                wo = tid&31 handles columns wo and wo+32
#define OCC 8   // channel chunk
__global__ void k_offconv(const float* __restrict__ x,
                          const float* __restrict__ w_off,
                          const float* __restrict__ b_off) {
    __shared__ float xs[OCC][3][66];     // rows ho-1..ho+1, cols -1..64
    __shared__ float wf[OCC][9][20];     // [cc][ky*3+kx][ko] padded to 20

    int b  = blockIdx.x >> 6;
    int ho = blockIdx.x & 63;
    int tid = threadIdx.x;               // 0..127
    int g   = tid >> 5;                  // 0..3
    int wo  = tid & 31;

    float acc0[5] = {0.f,0.f,0.f,0.f,0.f};
    float acc1[5] = {0.f,0.f,0.f,0.f,0.f};

    const float* xb = x + (size_t)b * C_ * H_ * W_;

    for (int c0 = 0; c0 < C_; c0 += OCC) {
        __syncthreads();
        // stage x rows (zero-padded)
        for (int it = tid; it < OCC * 3 * 66; it += 128) {
            int cc  = it / 198;
            int rem = it - cc * 198;
            int r   = rem / 66;
            int col = rem - r * 66;
            int hy  = ho - 1 + r;
            int wx  = col - 1;
            float v = 0.f;
            if ((unsigned)hy < (unsigned)H_ && (unsigned)wx < (unsigned)W_)
                v = xb[(c0 + cc) * (H_ * W_) + hy * W_ + wx];
            xs[cc][r][col] = v;
        }
        // stage weights (transposed, ko padded)
        for (int it = tid; it < OCC * 9 * 20; it += 128) {
            int cc  = it / 180;
            int rem = it - cc * 180;
            int kk  = rem / 20;
            int ko  = rem - kk * 20;
            float v = 0.f;
            if (ko < KO) v = w_off[((ko * C_) + (c0 + cc)) * 9 + kk];
            wf[cc][kk][ko] = v;
        }
        __syncthreads();

        #pragma unroll
        for (int cc = 0; cc < OCC; cc++) {
            #pragma unroll
            for (int r = 0; r < 3; r++) {
                float xa0 = xs[cc][r][wo];
                float xa1 = xs[cc][r][wo + 1];
                float xa2 = xs[cc][r][wo + 2];
                float xb0 = xs[cc][r][wo + 32];
                float xb1 = xs[cc][r][wo + 33];
                float xb2 = xs[cc][r][wo + 34];
                #pragma unroll
                for (int kx = 0; kx < 3; kx++) {
                    float xa = (kx == 0) ? xa0 : ((kx == 1) ? xa1 : xa2);
                    float xv = (kx == 0) ? xb0 : ((kx == 1) ? xb1 : xb2);
                    #pragma unroll
                    for (int j = 0; j < 5; j++) {
                        float wv = wf[cc][r * 3 + kx][g * 5 + j];
                        acc0[j] = fmaf(xa, wv, acc0[j]);
                        acc1[j] = fmaf(xv, wv, acc1[j]);
                    }
                }
            }
        }
    }

    #pragma unroll
    for (int j = 0; j < 5; j++) {
        int ko = g * 5 + j;
        if (ko < KO) {
            float bb = b_off[ko];
            int base = ((b * KO + ko) * H_ + ho) * W_;
            g_off[base + wo]      = acc0[j] + bb;
            g_off[base + wo + 32] = acc1[j] + bb;
        }
    }
}

// ---------------- kernel 2: fused deformable conv ----------------
// grid = B_*H_ (one output row: 128 couts x 64 pixels), blockDim = 256
// thread: cg = tid>>4 (cout group, 8 couts), pg = tid&15 (4 pixels)
// smem layout (floats): tapW[4*576] | vs[72*64] | ws[72*128] | tapI[4*576](int)
#define DCC 8
#define SM_TAPW 0
#define SM_VS   (4 * 576)                  // 2304
#define SM_WS   (SM_VS + 72 * 64)          // 6912
#define SM_TAPI (SM_WS + 72 * 128)         // 16128
#define SM_FLOATS (SM_TAPI + 4 * 576)      // 18432 floats = 73728 B

__global__ void k_deform(const float* __restrict__ x, float* __restrict__ out) {
    extern __shared__ float sm[];
    float* tapW = sm + SM_TAPW;
    float* vs   = sm + SM_VS;
    float* ws   = sm + SM_WS;
    int*   tapI = (int*)(sm + SM_TAPI);

    int b  = blockIdx.x >> 6;
    int ho = blockIdx.x & 63;
    int tid = threadIdx.x;       // 0..255
    int cg  = tid >> 4;          // 0..15
    int pg  = tid & 15;          // 0..15

    // ---- precompute bilinear taps for this row (shared by all channels) ----
    const float* goff = g_off + (size_t)(b * KO) * (H_ * W_) + ho * W_;
    for (int it = tid; it < 576; it += 256) {
        int k  = it >> 6;        // 0..8
        int wo = it & 63;
        float dy = goff[(2 * k)     * (H_ * W_) + wo];
        float dx = goff[(2 * k + 1) * (H_ * W_) + wo];
        float py = (float)(ho - 1 + (k / 3)) + dy;
        float px = (float)(wo - 1 + (k % 3)) + dx;
        float y0f = floorf(py), x0f = floorf(px);
        float wy = py - y0f,    wx = px - x0f;
        int y0 = (int)y0f, x0 = (int)x0f;
        int y1 = y0 + 1,   x1 = x0 + 1;
        float vy0 = (y0 >= 0 && y0 < H_) ? 1.f : 0.f;
        float vy1 = (y1 >= 0 && y1 < H_) ? 1.f : 0.f;
        float vx0 = (x0 >= 0 && x0 < W_) ? 1.f : 0.f;
        float vx1 = (x1 >= 0 && x1 < W_) ? 1.f : 0.f;
        int cy0 = min(max(y0, 0), H_ - 1), cy1 = min(max(y1, 0), H_ - 1);
        int cx0 = min(max(x0, 0), W_ - 1), cx1 = min(max(x1, 0), W_ - 1);
        tapI[0 * 576 + it] = cy0 * W_ + cx0;
        tapI[1 * 576 + it] = cy0 * W_ + cx1;
        tapI[2 * 576 + it] = cy1 * W_ + cx0;
        tapI[3 * 576 + it] = cy1 * W_ + cx1;
        tapW[0 * 576 + it] = (1.f - wy) * (1.f - wx) * vy0 * vx0;
        tapW[1 * 576 + it] = (1.f - wy) * wx         * vy0 * vx1;
        tapW[2 * 576 + it] = wy * (1.f - wx)         * vy1 * vx0;
        tapW[3 * 576 + it] = wy * wx                 * vy1 * vx1;
    }
    __syncthreads();

    float acc[8][4];
    #pragma unroll
    for (int i = 0; i < 8; i++)
        #pragma unroll
        for (int j = 0; j < 4; j++) acc[i][j] = 0.f;

    const float* xb = x + (size_t)b * C_ * H_ * W_;

    for (int c0 = 0; c0 < C_; c0 += DCC) {
        // stage weight slice: rows c0*9 .. c0*9+71, 128 couts each (contiguous)
        {
            const float4* wsrc = (const float4*)(g_wT + (size_t)c0 * 9 * COUT);
            float4* wdst = (float4*)ws;
            #pragma unroll
            for (int it = tid; it < 72 * COUT / 4; it += 256) wdst[it] = wsrc[it];
        }
        // gather val[cc][k][wo] with precomputed taps
        #pragma unroll
        for (int jj = 0; jj < 4608 / 256; jj++) {
            int it = tid + jj * 256;
            int cc = it / 576;
            int kw = it - cc * 576;
            const float* xc = xb + (size_t)(c0 + cc) * (H_ * W_);
            float v;
            v  = tapW[kw]            * xc[tapI[kw]];
            v += tapW[576 + kw]      * xc[tapI[576 + kw]];
            v += tapW[1152 + kw]     * xc[tapI[1152 + kw]];
            v += tapW[1728 + kw]     * xc[tapI[1728 + kw]];
            vs[cc * 576 + kw] = v;
        }
        __syncthreads();

        // micro-GEMM: acc[8 couts][4 pixels] over 72 (c,k) steps
        const float4* vs4 = (const float4*)vs;
        const float4* ws4 = (const float4*)ws;
        #pragma unroll 4
        for (int q = 0; q < 72; q++) {
            float4 v  = vs4[q * 16 + pg];
            float4 wa = ws4[q * 32 + (cg << 1)];
            float4 wb = ws4[q * 32 + (cg << 1) + 1];
            float vv[4] = {v.x, v.y, v.z, v.w};
            float ww[8] = {wa.x, wa.y, wa.z, wa.w, wb.x, wb.y, wb.z, wb.w};
            #pragma unroll
            for (int i = 0; i < 8; i++)
                #pragma unroll
                for (int j = 0; j < 4; j++)
                    acc[i][j] = fmaf(ww[i], vv[j], acc[i][j]);
        }
        __syncthreads();   // protect vs/ws before next chunk refill
    }

    // epilogue: out[b][cout][ho][wo], vectorized 4-pixel stores
    float* ob = out + ((size_t)(b * COUT) * H_ + ho) * W_;
    #pragma unroll
    for (int i = 0; i < 8; i++) {
        int cout = cg * 8 + i;
        float4 r = make_float4(acc[i][0], acc[i][1], acc[i][2], acc[i][3]);
        *(float4*)(ob + (size_t)cout * (H_ * W_) + pg * 4) = r;
    }
}

// ---------------- launcher ----------------
extern "C" void kernel_launch(void* const* d_in, const int* in_sizes, int n_in,
                              void* d_out, int out_size) {
    const float* x     = (const float*)d_in[0];   // (8,128,64,64)
    const float* w_off = (const float*)d_in[1];   // (18,128,3,3)
    const float* b_off = (const float*)d_in[2];   // (18,)
    const float* w_def = (const float*)d_in[3];   // (128,128,3,3)
    float* out = (float*)d_out;                   // (8,128,64,64)

    (void)in_sizes; (void)n_in; (void)out_size;

    // weight transpose for coalesced GEMM loads
    k_transpose_wdef<<<(COUT * CK + 255) / 256, 256>>>(w_def);

    // stage 1: offsets conv
    k_offconv<<<B_ * H_, 128>>>(x, w_off, b_off);

    // stage 2: fused deformable conv (needs >48KB dynamic smem)
    cudaFuncSetAttribute(k_deform, cudaFuncAttributeMaxDynamicSharedMemorySize,
                         SM_FLOATS * (int)sizeof(float));
    k_deform<<<B_ * H_, 256, SM_FLOATS * (int)sizeof(float)>>>(x, out);
}

// round 2
// speedup vs baseline: 1.0419x; 1.0419x over previous
#include <cuda_runtime.h>
#include <cstdint>

// Problem constants
#define B_   8
#define C_   128
#define H_   64
#define W_   64
#define COUT 128
#define KO   18          // offset channels (2*3*3)
#define K2_  9
#define CK   1152        // C_*K2_

// ---------------- f32x2 helpers (sm_100+) ----------------
__device__ __forceinline__ unsigned long long f32x2_bcast(float v) {
    unsigned long long r;
    asm("mov.b64 %0, {%1, %1};" : "=l"(r) : "f"(v));
    return r;
}
__device__ __forceinline__ unsigned long long f32x2_pack(float lo, float hi) {
    unsigned long long r;
    asm("mov.b64 %0, {%1, %2};" : "=l"(r) : "f"(lo), "f"(hi));
    return r;
}
__device__ __forceinline__ void f32x2_unpack(float& lo, float& hi, unsigned long long v) {
    asm("mov.b64 {%0, %1}, %2;" : "=f"(lo), "=f"(hi) : "l"(v));
}
__device__ __forceinline__ void ffma2(unsigned long long& d,
                                      unsigned long long a,
                                      unsigned long long b) {
    asm("fma.rn.f32x2 %0, %1, %2, %0;" : "+l"(d) : "l"(a), "l"(b));
}

// ---------------- device scratch (no allocs allowed) ----------------
__device__ float g_off[B_ * KO * H_ * W_];     // offsets conv result, [b][ko][h][w]
__device__ float g_wT[CK * COUT];              // w_def transposed: [(c*9+k)][cout]

// ---------------- kernel 0: transpose w_def -> g_wT ----------------
__global__ void k_transpose_wdef(const float* __restrict__ w_def) {
    int i = blockIdx.x * blockDim.x + threadIdx.x;      // over COUT*CK
    if (i < COUT * CK) {
        int cout = i / CK;
        int ck   = i - cout * CK;
        g_wT[ck * COUT + cout] = w_def[i];
    }
}

// ---------------- kernel 1: offsets = conv3x3(x, w_off) + b_off ----------------
// grid = B_*H_ blocks (one output row each), blockDim = 128
// g = tid>>5 (0..3) handles ko = g*5 .. g*5+4 (padded to 20), wo = tid&31
// pixel pair packed in f32x2: (col wo, col wo+32)
#define OCC 8   // channel chunk
__global__ void k_offconv(const float* __restrict__ x,
                          const float* __restrict__ w_off,
                          const float* __restrict__ b_off) {
    __shared__ float  xs[OCC][3][66];      // rows ho-1..ho+1, cols -1..64
    __shared__ float2 wf2[OCC][9][20];     // duplicated weight pair {w,w}

    int b  = blockIdx.x >> 6;
    int ho = blockIdx.x & 63;
    int tid = threadIdx.x;               // 0..127
    int g   = tid >> 5;                  // 0..3
    int wo  = tid & 31;

    unsigned long long accp[5];
    #pragma unroll
    for (int j = 0; j < 5; j++) accp[j] = 0ull;

    const float* xb = x + (size_t)b * C_ * H_ * W_;

    for (int c0 = 0; c0 < C_; c0 += OCC) {
        __syncthreads();
        // stage x rows (zero-padded)
        for (int it = tid; it < OCC * 3 * 66; it += 128) {
            int cc  = it / 198;
            int rem = it - cc * 198;
            int r   = rem / 66;
            int col = rem - r * 66;
            int hy  = ho - 1 + r;
            int wx  = col - 1;
            float v = 0.f;
            if ((unsigned)hy < (unsigned)H_ && (unsigned)wx < (unsigned)W_)
                v = xb[(c0 + cc) * (H_ * W_) + hy * W_ + wx];
            xs[cc][r][col] = v;
        }
        // stage weights duplicated (ko padded)
        for (int it = tid; it < OCC * 9 * 20; it += 128) {
            int cc  = it / 180;
            int rem = it - cc * 180;
            int kk  = rem / 20;
            int ko  = rem - kk * 20;
            float v = 0.f;
            if (ko < KO) v = w_off[((ko * C_) + (c0 + cc)) * 9 + kk];
            wf2[cc][kk][ko] = make_float2(v, v);
        }
        __syncthreads();

        #pragma unroll
        for (int cc = 0; cc < OCC; cc++) {
            #pragma unroll
            for (int r = 0; r < 3; r++) {
                unsigned long long xp0 = f32x2_pack(xs[cc][r][wo],     xs[cc][r][wo + 32]);
                unsigned long long xp1 = f32x2_pack(xs[cc][r][wo + 1], xs[cc][r][wo + 33]);
                unsigned long long xp2 = f32x2_pack(xs[cc][r][wo + 2], xs[cc][r][wo + 34]);
                #pragma unroll
                for (int kx = 0; kx < 3; kx++) {
                    unsigned long long xp = (kx == 0) ? xp0 : ((kx == 1) ? xp1 : xp2);
                    const unsigned long long* wrow =
                        (const unsigned long long*)&wf2[cc][r * 3 + kx][g * 5];
                    #pragma unroll
                    for (int j = 0; j < 5; j++)
                        ffma2(accp[j], xp, wrow[j]);
                }
            }
        }
    }

    #pragma unroll
    for (int j = 0; j < 5; j++) {
        int ko = g * 5 + j;
        if (ko < KO) {
            float a0, a1;
            f32x2_unpack(a0, a1, accp[j]);
            float bb = b_off[ko];
            int base = ((b * KO + ko) * H_ + ho) * W_;
            g_off[base + wo]      = a0 + bb;
            g_off[base + wo + 32] = a1 + bb;
        }
    }
}

// ---------------- kernel 2: fused deformable conv ----------------
// grid = B_*H_ (one output row: 128 couts x 64 pixels), blockDim = 128
// thread: cg = tid>>3 (0..15) -> couts cg*8..+7;  pg = tid&7 -> pixels pg*8..+7
// smem layout (floats): tapW[4*576] | vs[72*64] | ws[72*128] | tapI[4*576](int)
#define DCC 8
#define SM_TAPW 0
#define SM_VS   (4 * 576)                  // 2304
#define SM_WS   (SM_VS + 72 * 64)          // 6912
#define SM_TAPI (SM_WS + 72 * 128)         // 16128
#define SM_FLOATS (SM_TAPI + 4 * 576)      // 18432 floats = 73728 B

__global__ void __launch_bounds__(128, 3)
k_deform(const float* __restrict__ x, float* __restrict__ out) {
    extern __shared__ float sm[];
    float* tapW = sm + SM_TAPW;
    float* vs   = sm + SM_VS;
    float* ws   = sm + SM_WS;
    int*   tapI = (int*)(sm + SM_TAPI);

    int b  = blockIdx.x >> 6;
    int ho = blockIdx.x & 63;
    int tid = threadIdx.x;       // 0..127
    int cg  = tid >> 3;          // 0..15 (8 couts each)
    int pg  = tid & 7;           // 0..7  (8 pixels each)

    // ---- precompute bilinear taps for this row (shared by all channels) ----
    const float* goff = g_off + (size_t)(b * KO) * (H_ * W_) + ho * W_;
    for (int it = tid; it < 576; it += 128) {
        int k  = it >> 6;        // 0..8
        int wo = it & 63;
        float dy = goff[(2 * k)     * (H_ * W_) + wo];
        float dx = goff[(2 * k + 1) * (H_ * W_) + wo];
        float py = (float)(ho - 1 + (k / 3)) + dy;
        float px = (float)(wo - 1 + (k % 3)) + dx;
        float y0f = floorf(py), x0f = floorf(px);
        float wy = py - y0f,    wx = px - x0f;
        int y0 = (int)y0f, x0 = (int)x0f;
        int y1 = y0 + 1,   x1 = x0 + 1;
        float vy0 = (y0 >= 0 && y0 < H_) ? 1.f : 0.f;
        float vy1 = (y1 >= 0 && y1 < H_) ? 1.f : 0.f;
        float vx0 = (x0 >= 0 && x0 < W_) ? 1.f : 0.f;
        float vx1 = (x1 >= 0 && x1 < W_) ? 1.f : 0.f;
        int cy0 = min(max(y0, 0), H_ - 1), cy1 = min(max(y1, 0), H_ - 1);
        int cx0 = min(max(x0, 0), W_ - 1), cx1 = min(max(x1, 0), W_ - 1);
        tapI[0 * 576 + it] = cy0 * W_ + cx0;
        tapI[1 * 576 + it] = cy0 * W_ + cx1;
        tapI[2 * 576 + it] = cy1 * W_ + cx0;
        tapI[3 * 576 + it] = cy1 * W_ + cx1;
        tapW[0 * 576 + it] = (1.f - wy) * (1.f - wx) * vy0 * vx0;
        tapW[1 * 576 + it] = (1.f - wy) * wx         * vy0 * vx1;
        tapW[2 * 576 + it] = wy * (1.f - wx)         * vy1 * vx0;
        tapW[3 * 576 + it] = wy * wx                 * vy1 * vx1;
    }
    __syncthreads();

    // acc[coutpair 0..3][pixel 0..7] packed f32x2 along couts
    unsigned long long acc[4][8];
    #pragma unroll
    for (int i = 0; i < 4; i++)
        #pragma unroll
        for (int j = 0; j < 8; j++) acc[i][j] = 0ull;

    const float* xb = x + (size_t)b * C_ * H_ * W_;

    for (int c0 = 0; c0 < C_; c0 += DCC) {
        // stage weight slice: rows c0*9 .. c0*9+71, 128 couts each (contiguous)
        {
            const float4* wsrc = (const float4*)(g_wT + (size_t)c0 * 9 * COUT);
            float4* wdst = (float4*)ws;
            #pragma unroll
            for (int it = tid; it < 72 * COUT / 4; it += 128) wdst[it] = wsrc[it];
        }
        // gather val[cc][k][wo] with precomputed taps
        #pragma unroll
        for (int jj = 0; jj < 4608 / 128; jj++) {
            int it = tid + jj * 128;
            int cc = it / 576;
            int kw = it - cc * 576;
            const float* xc = xb + (size_t)(c0 + cc) * (H_ * W_);
            float v;
            v  = tapW[kw]            * xc[tapI[kw]];
            v += tapW[576 + kw]      * xc[tapI[576 + kw]];
            v += tapW[1152 + kw]     * xc[tapI[1152 + kw]];
            v += tapW[1728 + kw]     * xc[tapI[1728 + kw]];
            vs[cc * 576 + kw] = v;
        }
        __syncthreads();

        // micro-GEMM: acc[4 coutpairs][8 pixels] over 72 (c,k) steps, f32x2
        const float4* vs4 = (const float4*)vs;
        #pragma unroll 8
        for (int q = 0; q < 72; q++) {
            // weights: 8 consecutive couts -> 4 f32x2 pairs, loaded as 2x v2.b64
            const ulonglong2* wp = (const ulonglong2*)(ws + q * COUT + cg * 8);
            ulonglong2 w01 = wp[0];
            ulonglong2 w23 = wp[1];
            // pixels: 8 values, broadcast-packed
            float4 v0 = vs4[q * 16 + pg * 2];
            float4 v1 = vs4[q * 16 + pg * 2 + 1];
            unsigned long long vp[8];
            vp[0] = f32x2_bcast(v0.x); vp[1] = f32x2_bcast(v0.y);
            vp[2] = f32x2_bcast(v0.z); vp[3] = f32x2_bcast(v0.w);
            vp[4] = f32x2_bcast(v1.x); vp[5] = f32x2_bcast(v1.y);
            vp[6] = f32x2_bcast(v1.z); vp[7] = f32x2_bcast(v1.w);
            #pragma unroll
            for (int p = 0; p < 8; p++) {
                ffma2(acc[0][p], w01.x, vp[p]);
                ffma2(acc[1][p], w01.y, vp[p]);
                ffma2(acc[2][p], w23.x, vp[p]);
                ffma2(acc[3][p], w23.y, vp[p]);
            }
        }
        __syncthreads();   // protect vs/ws before next chunk refill
    }

    // epilogue: out[b][cout][ho][wo], 8 pixels per cout as 2x float4
    float* ob = out + ((size_t)(b * COUT) * H_ + ho) * W_;
    #pragma unroll
    for (int cp = 0; cp < 4; cp++) {
        float r0[8], r1[8];
        #pragma unroll
        for (int p = 0; p < 8; p++) f32x2_unpack(r0[p], r1[p], acc[cp][p]);
        int cout0 = cg * 8 + cp * 2;
        float* o0 = ob + (size_t)cout0 * (H_ * W_) + pg * 8;
        float* o1 = o0 + (size_t)(H_ * W_);
        *(float4*)(o0)     = make_float4(r0[0], r0[1], r0[2], r0[3]);
        *(float4*)(o0 + 4) = make_float4(r0[4], r0[5], r0[6], r0[7]);
        *(float4*)(o1)     = make_float4(r1[0], r1[1], r1[2], r1[3]);
        *(float4*)(o1 + 4) = make_float4(r1[4], r1[5], r1[6], r1[7]);
    }
}

// ---------------- launcher ----------------
extern "C" void kernel_launch(void* const* d_in, const int* in_sizes, int n_in,
                              void* d_out, int out_size) {
    const float* x     = (const float*)d_in[0];   // (8,128,64,64)
    const float* w_off = (const float*)d_in[1];   // (18,128,3,3)
    const float* b_off = (const float*)d_in[2];   // (18,)
    const float* w_def = (const float*)d_in[3];   // (128,128,3,3)
    float* out = (float*)d_out;                   // (8,128,64,64)

    (void)in_sizes; (void)n_in; (void)out_size;

    // weight transpose for coalesced GEMM loads
    k_transpose_wdef<<<(COUT * CK + 255) / 256, 256>>>(w_def);

    // stage 1: offsets conv
    k_offconv<<<B_ * H_, 128>>>(x, w_off, b_off);

    // stage 2: fused deformable conv (needs >48KB dynamic smem)
    cudaFuncSetAttribute(k_deform, cudaFuncAttributeMaxDynamicSharedMemorySize,
                         SM_FLOATS * (int)sizeof(float));
    k_deform<<<B_ * H_, 128, SM_FLOATS * (int)sizeof(float)>>>(x, out);
}

// round 4
// speedup vs baseline: 1.2733x; 1.2221x over previous
#include <cuda_runtime.h>
#include <cuda_bf16.h>
#include <cstdint>

// Problem constants
#define B_   8
#define C_   128
#define H_   64
#define W_   64
#define COUT 128
#define KO   18
#define CK   1152          // C_*9
#define KC   64            // K per chunk
#define NCHUNK (CK / KC)   // 18

// ---------------- f32x2 helpers (offconv) ----------------
__device__ __forceinline__ unsigned long long f32x2_pack(float lo, float hi) {
    unsigned long long r;
    asm("mov.b64 %0, {%1, %2};" : "=l"(r) : "f"(lo), "f"(hi));
    return r;
}
__device__ __forceinline__ void f32x2_unpack(float& lo, float& hi, unsigned long long v) {
    asm("mov.b64 {%0, %1}, %2;" : "=f"(lo), "=f"(hi) : "l"(v));
}
__device__ __forceinline__ void ffma2(unsigned long long& d, unsigned long long a,
                                      unsigned long long b) {
    asm("fma.rn.f32x2 %0, %1, %2, %0;" : "+l"(d) : "l"(a), "l"(b));
}

__device__ __forceinline__ uint32_t smem_to_u32(const void* p) {
    uint32_t a;
    asm("{ .reg .u64 t; cvta.to.shared.u64 t, %1; cvt.u32.u64 %0, t; }" : "=r"(a) : "l"(p));
    return a;
}

// ldmatrix x4 (non-transposed)
#define LDSM4(r0, r1, r2, r3, addr) \
    asm volatile("ldmatrix.sync.aligned.m8n8.x4.shared.b16 {%0,%1,%2,%3}, [%4];" \
                 : "=r"(r0), "=r"(r1), "=r"(r2), "=r"(r3) : "r"(addr))

// bf16 mma with fp32 accumulate
#define MMA16816(c, a0, a1, a2, a3, b0, b1) \
    asm volatile("mma.sync.aligned.m16n8k16.row.col.f32.bf16.bf16.f32 " \
                 "{%0,%1,%2,%3},{%4,%5,%6,%7},{%8,%9},{%0,%1,%2,%3};" \
                 : "+f"((c)[0]), "+f"((c)[1]), "+f"((c)[2]), "+f"((c)[3]) \
                 : "r"(a0), "r"(a1), "r"(a2), "r"(a3), "r"(b0), "r"(b1))

// ---------------- device scratch ----------------
__device__ float g_off[B_ * KO * H_ * W_];
__device__ __align__(16) __nv_bfloat16 g_whi[COUT * CK];   // [cout][ck]
__device__ __align__(16) __nv_bfloat16 g_wlo[COUT * CK];

// ---------------- kernel 0: bf16-split weights ----------------
__global__ void k_split_wdef(const float* __restrict__ w_def) {
    int i = blockIdx.x * blockDim.x + threadIdx.x;
    if (i < COUT * CK) {
        float w = w_def[i];
        __nv_bfloat16 hi = __float2bfloat16(w);
        __nv_bfloat16 lo = __float2bfloat16(w - __bfloat162float(hi));
        g_whi[i] = hi;
        g_wlo[i] = lo;
    }
}

// ---------------- kernel 1: offsets conv ----------------
#define OCC 8
__global__ void k_offconv(const float* __restrict__ x,
                          const float* __restrict__ w_off,
                          const float* __restrict__ b_off) {
    __shared__ float  xs[OCC][3][66];
    __shared__ float2 wf2[OCC][9][20];

    int b  = blockIdx.x >> 6;
    int ho = blockIdx.x & 63;
    int tid = threadIdx.x;
    int g   = tid >> 5;
    int wo  = tid & 31;

    unsigned long long accp[5];
    #pragma unroll
    for (int j = 0; j < 5; j++) accp[j] = 0ull;

    const float* xb = x + (size_t)b * C_ * H_ * W_;

    for (int c0 = 0; c0 < C_; c0 += OCC) {
        __syncthreads();
        for (int it = tid; it < OCC * 3 * 66; it += 128) {
            int cc  = it / 198;
            int rem = it - cc * 198;
            int r   = rem / 66;
            int col = rem - r * 66;
            int hy  = ho - 1 + r;
            int wx  = col - 1;
            float v = 0.f;
            if ((unsigned)hy < (unsigned)H_ && (unsigned)wx < (unsigned)W_)
                v = xb[(c0 + cc) * (H_ * W_) + hy * W_ + wx];
            xs[cc][r][col] = v;
        }
        for (int it = tid; it < OCC * 9 * 20; it += 128) {
            int cc  = it / 180;
            int rem = it - cc * 180;
            int kk  = rem / 20;
            int ko  = rem - kk * 20;
            float v = 0.f;
            if (ko < KO) v = w_off[((ko * C_) + (c0 + cc)) * 9 + kk];
            wf2[cc][kk][ko] = make_float2(v, v);
        }
        __syncthreads();

        #pragma unroll
        for (int cc = 0; cc < OCC; cc++) {
            #pragma unroll
            for (int r = 0; r < 3; r++) {
                unsigned long long xp0 = f32x2_pack(xs[cc][r][wo],     xs[cc][r][wo + 32]);
                unsigned long long xp1 = f32x2_pack(xs[cc][r][wo + 1], xs[cc][r][wo + 33]);
                unsigned long long xp2 = f32x2_pack(xs[cc][r][wo + 2], xs[cc][r][wo + 34]);
                #pragma unroll
                for (int kx = 0; kx < 3; kx++) {
                    unsigned long long xp = (kx == 0) ? xp0 : ((kx == 1) ? xp1 : xp2);
                    const unsigned long long* wrow =
                        (const unsigned long long*)&wf2[cc][r * 3 + kx][g * 5];
                    #pragma unroll
                    for (int j = 0; j < 5; j++) ffma2(accp[j], xp, wrow[j]);
                }
            }
        }
    }
    #pragma unroll
    for (int j = 0; j < 5; j++) {
        int ko = g * 5 + j;
        if (ko < KO) {
            float a0, a1;
            f32x2_unpack(a0, a1, accp[j]);
            float bb = b_off[ko];
            int base = ((b * KO + ko) * H_ + ho) * W_;
            g_off[base + wo]      = a0 + bb;
            g_off[base + wo + 32] = a1 + bb;
        }
    }
}

// ---------------- kernel 2: deformable conv via mma.sync bf16 3x-split ----------------
// grid = B_*H_ (one (b,ho) tile: D[128 cout][64 px], K=1152), blockDim = 256 (8 warps)
// warp w: m-stripe m0 = w*16, full n=64.
// SMEM (byte offsets), all tiles 144B row pitch (conflict-free ldmatrix):
#define PITCH 144
#define SA_HI 0                         // 128 rows
#define SA_LO (SA_HI + 128 * PITCH)     // 18432
#define SB_HI (SA_LO + 128 * PITCH)     // 36864, 64 rows
#define SB_LO (SB_HI + 64 * PITCH)      // 46080
#define STAPW (SB_LO + 64 * PITCH)      // 55296, 4*576 floats
#define STAPI (STAPW + 4 * 576 * 4)     // 64512, 4*576 ints
#define SBYTES (STAPI + 4 * 576 * 4)    // 73728

__global__ void __launch_bounds__(256)
k_deform(const float* __restrict__ x, float* __restrict__ out) {
    extern __shared__ __align__(16) char smc[];
    uint32_t sb = smem_to_u32(smc);
    float* tapW = (float*)(smc + STAPW);
    int*   tapI = (int*)(smc + STAPI);

    int b   = blockIdx.x >> 6;
    int ho  = blockIdx.x & 63;
    int tid = threadIdx.x;
    int wid = tid >> 5;
    int lane = tid & 31;

    // ---- precompute bilinear taps for this row ----
    const float* goff = g_off + (size_t)(b * KO) * (H_ * W_) + ho * W_;
    for (int it = tid; it < 576; it += 256) {
        int k  = it >> 6;
        int wo = it & 63;
        float dy = goff[(2 * k)     * (H_ * W_) + wo];
        float dx = goff[(2 * k + 1) * (H_ * W_) + wo];
        float py = (float)(ho - 1 + (k / 3)) + dy;
        float px = (float)(wo - 1 + (k % 3)) + dx;
        float y0f = floorf(py), x0f = floorf(px);
        float wy = py - y0f,    wx = px - x0f;
        int y0 = (int)y0f, x0 = (int)x0f;
        int y1 = y0 + 1,   x1 = x0 + 1;
        float vy0 = (y0 >= 0 && y0 < H_) ? 1.f : 0.f;
        float vy1 = (y1 >= 0 && y1 < H_) ? 1.f : 0.f;
        float vx0 = (x0 >= 0 && x0 < W_) ? 1.f : 0.f;
        float vx1 = (x1 >= 0 && x1 < W_) ? 1.f : 0.f;
        int cy0 = min(max(y0, 0), H_ - 1), cy1 = min(max(y1, 0), H_ - 1);
        int cx0 = min(max(x0, 0), W_ - 1), cx1 = min(max(x1, 0), W_ - 1);
        tapI[0 * 576 + it] = cy0 * W_ + cx0;
        tapI[1 * 576 + it] = cy0 * W_ + cx1;
        tapI[2 * 576 + it] = cy1 * W_ + cx0;
        tapI[3 * 576 + it] = cy1 * W_ + cx1;
        tapW[0 * 576 + it] = (1.f - wy) * (1.f - wx) * vy0 * vx0;
        tapW[1 * 576 + it] = (1.f - wy) * wx         * vy0 * vx1;
        tapW[2 * 576 + it] = wy * (1.f - wx)         * vy1 * vx0;
        tapW[3 * 576 + it] = wy * wx                 * vy1 * vx1;
    }

    // accumulators: 8 n8-tiles x 4 regs
    float c[8][4];
    #pragma unroll
    for (int i = 0; i < 8; i++)
        #pragma unroll
        for (int j = 0; j < 4; j++) c[i][j] = 0.f;

    const float* xb = x + (size_t)b * C_ * H_ * W_;
    const int n   = tid & 63;       // pixel this thread gathers
    const int t4  = tid >> 6;       // 0..3 -> k_local mod 4

    // ldmatrix lane address components
    const int g8  = lane >> 3;      // matrix index 0..3
    const int lr  = lane & 7;
    const int m0  = wid * 16;
    // A (m16k16): mat0 rows0-7 k0 | mat1 rows8-15 k0 | mat2 rows0-7 k8 | mat3 rows8-15 k8
    const uint32_t a_row  = (uint32_t)(m0 + lr + (g8 & 1) * 8);
    const uint32_t a_koff = (uint32_t)((g8 >> 1) * 8);
    // B (n16k16): mat0 n0-7 k0 | mat1 n0-7 k8 | mat2 n8-15 k0 | mat3 n8-15 k8
    const uint32_t b_row  = (uint32_t)(lr + (g8 >> 1) * 8);
    const uint32_t b_koff = (uint32_t)((g8 & 1) * 8);

    for (int chunk = 0; chunk < NCHUNK; chunk++) {
        __syncthreads();   // previous mma reads done before restaging

        // stage A (weights hi/lo): 128 rows x 64 bf16 (128B) each
        #pragma unroll
        for (int jj = 0; jj < 4; jj++) {
            int it  = tid + jj * 256;       // 0..1023
            int m   = it >> 3;
            int c16 = it & 7;
            int so  = m * PITCH + c16 * 16;
            const char* sh = (const char*)g_whi + (size_t)m * (CK * 2) + chunk * (KC * 2) + c16 * 16;
            const char* sl = (const char*)g_wlo + (size_t)m * (CK * 2) + chunk * (KC * 2) + c16 * 16;
            *(uint4*)(smc + SA_HI + so) = *(const uint4*)sh;
            *(uint4*)(smc + SA_LO + so) = *(const uint4*)sl;
        }

        // gather + bf16-split B: vs[n][k_local]
        #pragma unroll 4
        for (int jj = 0; jj < 16; jj++) {
            int k_local = jj * 4 + t4;
            int kk = chunk * KC + k_local;
            int cch = kk / 9;
            int k9  = kk - cch * 9;
            const float* xc = xb + (size_t)cch * (H_ * W_);
            int tb = k9 * 64 + n;
            float v;
            v  = tapW[tb]        * xc[tapI[tb]];
            v += tapW[576 + tb]  * xc[tapI[576 + tb]];
            v += tapW[1152 + tb] * xc[tapI[1152 + tb]];
            v += tapW[1728 + tb] * xc[tapI[1728 + tb]];
            __nv_bfloat16 hi = __float2bfloat16(v);
            __nv_bfloat16 lo = __float2bfloat16(v - __bfloat162float(hi));
            int so = n * PITCH + k_local * 2;
            *(__nv_bfloat16*)(smc + SB_HI + so) = hi;
            *(__nv_bfloat16*)(smc + SB_LO + so) = lo;
        }
        __syncthreads();

        // MMA phase: 3 split terms x 4 k16-steps x 8 n8-tiles
        #pragma unroll
        for (int term = 0; term < 3; term++) {
            uint32_t Ab = sb + ((term == 2) ? SA_LO : SA_HI);
            uint32_t Bb = sb + ((term == 1) ? SB_LO : SB_HI);
            #pragma unroll
            for (int ks = 0; ks < 4; ks++) {
                uint32_t a0, a1, a2, a3;
                LDSM4(a0, a1, a2, a3,
                      Ab + a_row * PITCH + (ks * 16 + a_koff) * 2);
                #pragma unroll
                for (int ng = 0; ng < 4; ng++) {
                    uint32_t b0, b1, b2, b3;
                    LDSM4(b0, b1, b2, b3,
                          Bb + (ng * 16 + b_row) * PITCH + (ks * 16 + b_koff) * 2);
                    MMA16816(c[ng * 2],     a0, a1, a2, a3, b0, b1);
                    MMA16816(c[ng * 2 + 1], a0, a1, a2, a3, b2, b3);
                }
            }
        }
    }

    // epilogue: thread t of warp -> rows m0 + t/4 and m0 + t/4 + 8, cols 2*(t%4)
    {
        int r0  = m0 + (lane >> 2);
        int col = 2 * (lane & 3);
        float* ob = out + (((size_t)(b * COUT)) * H_ + ho) * W_;
        #pragma unroll
        for (int t8 = 0; t8 < 8; t8++) {
            int nbase = t8 * 8 + col;
            float* p0 = ob + (size_t)r0 * (H_ * W_) + nbase;
            float* p1 = ob + (size_t)(r0 + 8) * (H_ * W_) + nbase;
            *(float2*)p0 = make_float2(c[t8][0], c[t8][1]);
            *(float2*)p1 = make_float2(c[t8][2], c[t8][3]);
        }
    }
}

// ---------------- launcher ----------------
extern "C" void kernel_launch(void* const* d_in, const int* in_sizes, int n_in,
                              void* d_out, int out_size) {
    const float* x     = (const float*)d_in[0];
    const float* w_off = (const float*)d_in[1];
    const float* b_off = (const float*)d_in[2];
    const float* w_def = (const float*)d_in[3];
    float* out = (float*)d_out;
    (void)in_sizes; (void)n_in; (void)out_size;

    k_split_wdef<<<(COUT * CK + 255) / 256, 256>>>(w_def);
    k_offconv<<<B_ * H_, 128>>>(x, w_off, b_off);

    cudaFuncSetAttribute(k_deform, cudaFuncAttributeMaxDynamicSharedMemorySize, SBYTES);
    k_deform<<<B_ * H_, 256, SBYTES>>>(x, out);
}

// round 5
// speedup vs baseline: 1.6092x; 1.2638x over previous
#include <cuda_runtime.h>
#include <cuda_fp16.h>
#include <cstdint>

// Problem constants
#define B_   8
#define C_   128
#define H_   64
#define W_   64
#define COUT 128
#define KO   18
#define CK   1152          // C_*9
#define KC   64            // K per chunk
#define NCHUNK (CK / KC)   // 18

// ---------------- f32x2 helpers (offconv) ----------------
__device__ __forceinline__ unsigned long long f32x2_pack(float lo, float hi) {
    unsigned long long r;
    asm("mov.b64 %0, {%1, %2};" : "=l"(r) : "f"(lo), "f"(hi));
    return r;
}
__device__ __forceinline__ void f32x2_unpack(float& lo, float& hi, unsigned long long v) {
    asm("mov.b64 {%0, %1}, %2;" : "=f"(lo), "=f"(hi) : "l"(v));
}
__device__ __forceinline__ void ffma2(unsigned long long& d, unsigned long long a,
                                      unsigned long long b) {
    asm("fma.rn.f32x2 %0, %1, %2, %0;" : "+l"(d) : "l"(a), "l"(b));
}

__device__ __forceinline__ uint32_t smem_to_u32(const void* p) {
    uint32_t a;
    asm("{ .reg .u64 t; cvta.to.shared.u64 t, %1; cvt.u32.u64 %0, t; }" : "=r"(a) : "l"(p));
    return a;
}

// ldmatrix x4 (non-transposed)
#define LDSM4(r0, r1, r2, r3, addr) \
    asm volatile("ldmatrix.sync.aligned.m8n8.x4.shared.b16 {%0,%1,%2,%3}, [%4];" \
                 : "=r"(r0), "=r"(r1), "=r"(r2), "=r"(r3) : "r"(addr))

// fp16 mma with fp32 accumulate
#define MMA16816(c, a0, a1, a2, a3, b0, b1) \
    asm volatile("mma.sync.aligned.m16n8k16.row.col.f32.f16.f16.f32 " \
                 "{%0,%1,%2,%3},{%4,%5,%6,%7},{%8,%9},{%0,%1,%2,%3};" \
                 : "+f"((c)[0]), "+f"((c)[1]), "+f"((c)[2]), "+f"((c)[3]) \
                 : "r"(a0), "r"(a1), "r"(a2), "r"(a3), "r"(b0), "r"(b1))

// ---------------- device scratch ----------------
__device__ float g_off[B_ * KO * H_ * W_];
__device__ __align__(16) __half g_wh[COUT * CK];   // fp16 weights [cout][ck]

// ---------------- kernel 0: fp16 weights ----------------
__global__ void k_prep_w(const float* __restrict__ w_def) {
    int i = blockIdx.x * blockDim.x + threadIdx.x;
    if (i < COUT * CK) g_wh[i] = __float2half(w_def[i]);
}

// ---------------- kernel 1: offsets conv ----------------
#define OCC 8
__global__ void k_offconv(const float* __restrict__ x,
                          const float* __restrict__ w_off,
                          const float* __restrict__ b_off) {
    __shared__ float  xs[OCC][3][66];
    __shared__ float2 wf2[OCC][9][20];

    int b  = blockIdx.x >> 6;
    int ho = blockIdx.x & 63;
    int tid = threadIdx.x;
    int g   = tid >> 5;
    int wo  = tid & 31;

    unsigned long long accp[5];
    #pragma unroll
    for (int j = 0; j < 5; j++) accp[j] = 0ull;

    const float* xb = x + (size_t)b * C_ * H_ * W_;

    for (int c0 = 0; c0 < C_; c0 += OCC) {
        __syncthreads();
        for (int it = tid; it < OCC * 3 * 66; it += 128) {
            int cc  = it / 198;
            int rem = it - cc * 198;
            int r   = rem / 66;
            int col = rem - r * 66;
            int hy  = ho - 1 + r;
            int wx  = col - 1;
            float v = 0.f;
            if ((unsigned)hy < (unsigned)H_ && (unsigned)wx < (unsigned)W_)
                v = xb[(c0 + cc) * (H_ * W_) + hy * W_ + wx];
            xs[cc][r][col] = v;
        }
        for (int it = tid; it < OCC * 9 * 20; it += 128) {
            int cc  = it / 180;
            int rem = it - cc * 180;
            int kk  = rem / 20;
            int ko  = rem - kk * 20;
            float v = 0.f;
            if (ko < KO) v = w_off[((ko * C_) + (c0 + cc)) * 9 + kk];
            wf2[cc][kk][ko] = make_float2(v, v);
        }
        __syncthreads();

        #pragma unroll
        for (int cc = 0; cc < OCC; cc++) {
            #pragma unroll
            for (int r = 0; r < 3; r++) {
                unsigned long long xp0 = f32x2_pack(xs[cc][r][wo],     xs[cc][r][wo + 32]);
                unsigned long long xp1 = f32x2_pack(xs[cc][r][wo + 1], xs[cc][r][wo + 33]);
                unsigned long long xp2 = f32x2_pack(xs[cc][r][wo + 2], xs[cc][r][wo + 34]);
                #pragma unroll
                for (int kx = 0; kx < 3; kx++) {
                    unsigned long long xp = (kx == 0) ? xp0 : ((kx == 1) ? xp1 : xp2);
                    const unsigned long long* wrow =
                        (const unsigned long long*)&wf2[cc][r * 3 + kx][g * 5];
                    #pragma unroll
                    for (int j = 0; j < 5; j++) ffma2(accp[j], xp, wrow[j]);
                }
            }
        }
    }
    #pragma unroll
    for (int j = 0; j < 5; j++) {
        int ko = g * 5 + j;
        if (ko < KO) {
            float a0, a1;
            f32x2_unpack(a0, a1, accp[j]);
            float bb = b_off[ko];
            int base = ((b * KO + ko) * H_ + ho) * W_;
            g_off[base + wo]      = a0 + bb;
            g_off[base + wo + 32] = a1 + bb;
        }
    }
}

// ---------------- kernel 2: deformable conv, fp16 single-term mma.sync ----------------
// grid = B_*H_ (one (b,ho) tile: D[128 cout][64 px], K=1152), blockDim = 256 (8 warps)
// SMEM (byte offsets), tiles at 144B row pitch (conflict-free ldmatrix):
#define PITCH 144
#define SA    0                         // 128 rows x 64 fp16
#define SB    (SA + 128 * PITCH)        // 18432, 64 rows x 64 fp16
#define STAPW (SB + 64 * PITCH)         // 27648, 4*576 floats
#define STAPI (STAPW + 4 * 576 * 4)     // 36864, 4*576 ints
#define SBYTES (STAPI + 4 * 576 * 4)    // 46080

__global__ void __launch_bounds__(256)
k_deform(const float* __restrict__ x, float* __restrict__ out) {
    extern __shared__ __align__(16) char smc[];
    uint32_t sb = smem_to_u32(smc);
    float* tapW = (float*)(smc + STAPW);
    int*   tapI = (int*)(smc + STAPI);

    int b   = blockIdx.x >> 6;
    int ho  = blockIdx.x & 63;
    int tid = threadIdx.x;
    int wid = tid >> 5;
    int lane = tid & 31;

    // ---- precompute bilinear taps for this row ----
    const float* goff = g_off + (size_t)(b * KO) * (H_ * W_) + ho * W_;
    for (int it = tid; it < 576; it += 256) {
        int k  = it >> 6;
        int wo = it & 63;
        float dy = goff[(2 * k)     * (H_ * W_) + wo];
        float dx = goff[(2 * k + 1) * (H_ * W_) + wo];
        float py = (float)(ho - 1 + (k / 3)) + dy;
        float px = (float)(wo - 1 + (k % 3)) + dx;
        float y0f = floorf(py), x0f = floorf(px);
        float wy = py - y0f,    wx = px - x0f;
        int y0 = (int)y0f, x0 = (int)x0f;
        int y1 = y0 + 1,   x1 = x0 + 1;
        float vy0 = (y0 >= 0 && y0 < H_) ? 1.f : 0.f;
        float vy1 = (y1 >= 0 && y1 < H_) ? 1.f : 0.f;
        float vx0 = (x0 >= 0 && x0 < W_) ? 1.f : 0.f;
        float vx1 = (x1 >= 0 && x1 < W_) ? 1.f : 0.f;
        int cy0 = min(max(y0, 0), H_ - 1), cy1 = min(max(y1, 0), H_ - 1);
        int cx0 = min(max(x0, 0), W_ - 1), cx1 = min(max(x1, 0), W_ - 1);
        tapI[0 * 576 + it] = cy0 * W_ + cx0;
        tapI[1 * 576 + it] = cy0 * W_ + cx1;
        tapI[2 * 576 + it] = cy1 * W_ + cx0;
        tapI[3 * 576 + it] = cy1 * W_ + cx1;
        tapW[0 * 576 + it] = (1.f - wy) * (1.f - wx) * vy0 * vx0;
        tapW[1 * 576 + it] = (1.f - wy) * wx         * vy0 * vx1;
        tapW[2 * 576 + it] = wy * (1.f - wx)         * vy1 * vx0;
        tapW[3 * 576 + it] = wy * wx                 * vy1 * vx1;
    }

    // accumulators: 8 n8-tiles x 4 regs
    float c[8][4];
    #pragma unroll
    for (int i = 0; i < 8; i++)
        #pragma unroll
        for (int j = 0; j < 4; j++) c[i][j] = 0.f;

    const float* xb = x + (size_t)b * C_ * H_ * W_;
    const int n   = tid & 63;       // pixel this thread gathers
    const int t4  = tid >> 6;       // 0..3 -> k_local mod 4

    // ldmatrix lane address components
    const int g8  = lane >> 3;      // matrix index 0..3
    const int lr  = lane & 7;
    const int m0  = wid * 16;
    const uint32_t a_row  = (uint32_t)(m0 + lr + (g8 & 1) * 8);
    const uint32_t a_koff = (uint32_t)((g8 >> 1) * 8);
    const uint32_t b_row  = (uint32_t)(lr + (g8 >> 1) * 8);
    const uint32_t b_koff = (uint32_t)((g8 & 1) * 8);

    for (int chunk = 0; chunk < NCHUNK; chunk++) {
        __syncthreads();   // previous mma reads done before restaging

        // stage A (fp16 weights): 128 rows x 128B
        #pragma unroll
        for (int jj = 0; jj < 4; jj++) {
            int it  = tid + jj * 256;       // 0..1023
            int m   = it >> 3;
            int c16 = it & 7;
            const char* sh = (const char*)g_wh + (size_t)m * (CK * 2) + chunk * (KC * 2) + c16 * 16;
            *(uint4*)(smc + SA + m * PITCH + c16 * 16) = *(const uint4*)sh;
        }

        // gather B (fp16): vs[n][k_local]
        #pragma unroll 4
        for (int jj = 0; jj < 16; jj++) {
            int k_local = jj * 4 + t4;
            int kk = chunk * KC + k_local;
            int cch = kk / 9;
            int k9  = kk - cch * 9;
            const float* xc = xb + (size_t)cch * (H_ * W_);
            int tb = k9 * 64 + n;
            float v;
            v  = tapW[tb]        * xc[tapI[tb]];
            v += tapW[576 + tb]  * xc[tapI[576 + tb]];
            v += tapW[1152 + tb] * xc[tapI[1152 + tb]];
            v += tapW[1728 + tb] * xc[tapI[1728 + tb]];
            *(__half*)(smc + SB + n * PITCH + k_local * 2) = __float2half(v);
        }
        __syncthreads();

        // MMA phase: 4 k16-steps x 8 n8-tiles, single fp16 term
        #pragma unroll
        for (int ks = 0; ks < 4; ks++) {
            uint32_t a0, a1, a2, a3;
            LDSM4(a0, a1, a2, a3,
                  sb + SA + a_row * PITCH + (ks * 16 + a_koff) * 2);
            #pragma unroll
            for (int ng = 0; ng < 4; ng++) {
                uint32_t b0, b1, b2, b3;
                LDSM4(b0, b1, b2, b3,
                      sb + SB + (ng * 16 + b_row) * PITCH + (ks * 16 + b_koff) * 2);
                MMA16816(c[ng * 2],     a0, a1, a2, a3, b0, b1);
                MMA16816(c[ng * 2 + 1], a0, a1, a2, a3, b2, b3);
            }
        }
    }

    // epilogue
    {
        int r0  = m0 + (lane >> 2);
        int col = 2 * (lane & 3);
        float* ob = out + (((size_t)(b * COUT)) * H_ + ho) * W_;
        #pragma unroll
        for (int t8 = 0; t8 < 8; t8++) {
            int nbase = t8 * 8 + col;
            float* p0 = ob + (size_t)r0 * (H_ * W_) + nbase;
            float* p1 = ob + (size_t)(r0 + 8) * (H_ * W_) + nbase;
            *(float2*)p0 = make_float2(c[t8][0], c[t8][1]);
            *(float2*)p1 = make_float2(c[t8][2], c[t8][3]);
        }
    }
}

// ---------------- launcher ----------------
extern "C" void kernel_launch(void* const* d_in, const int* in_sizes, int n_in,
                              void* d_out, int out_size) {
    const float* x     = (const float*)d_in[0];
    const float* w_off = (const float*)d_in[1];
    const float* b_off = (const float*)d_in[2];
    const float* w_def = (const float*)d_in[3];
    float* out = (float*)d_out;
    (void)in_sizes; (void)n_in; (void)out_size;

    k_prep_w<<<(COUT * CK + 255) / 256, 256>>>(w_def);
    k_offconv<<<B_ * H_, 128>>>(x, w_off, b_off);

    cudaFuncSetAttribute(k_deform, cudaFuncAttributeMaxDynamicSharedMemorySize, SBYTES);
    k_deform<<<B_ * H_, 256, SBYTES>>>(x, out);
}